// round 16
// baseline (speedup 1.0000x reference)
#include <cuda_runtime.h>
#include <math.h>

// Problem dims
#define SQ  512
#define BB  64
#define HH  512
#define G4  2048

// Decomposition: 128 blocks = dir(2) x batch-group(2, 32 batches) x slice(32, 16 units)
#define NBG   32      // batches per group
#define NUNIT 16      // hidden units per slice
#define NCOL  64      // gate columns per block (4 gates x 16 units)

// ---------------------------------------------------------------------------
// Device scratch (allocation-free rule: __device__ globals)
// ---------------------------------------------------------------------------
// gates layout: [dir][slice(32)][t(512)][b(64)][64]  (64 = 4 gates x 16 units)
__device__ float g_gates[2u * SQ * BB * G4];
__device__ float g_x1[(size_t)SQ * BB * 1024];        // layer output, tf32-rounded bits
__device__ float g_h[2][2][BB][HH];                   // double-buffered h (tf32-rounded)
__device__ float g_wtf[2][2][2048 * 1024];            // W_ih tf32 bits [layer][dir][j*K+k]
__device__ float g_xin[(size_t)SQ * BB * 256];        // input_seq transposed+tf32
__device__ __align__(128) unsigned g_flag[4][32];     // per-group step flags (1 line/group)

// ---------------------------------------------------------------------------
// Helpers
// ---------------------------------------------------------------------------
__device__ __forceinline__ unsigned f2tf(float x) {
    unsigned u; asm("cvt.rna.tf32.f32 %0, %1;" : "=r"(u) : "f"(x)); return u;
}
__device__ __forceinline__ unsigned fu(float x) { return __float_as_uint(x); }

__device__ __forceinline__ void mma_tf32(float* c, const unsigned* a, const unsigned* b) {
    asm("mma.sync.aligned.m16n8k8.row.col.f32.tf32.tf32.f32 "
        "{%0,%1,%2,%3}, {%4,%5,%6,%7}, {%8,%9}, {%0,%1,%2,%3};"
        : "+f"(c[0]), "+f"(c[1]), "+f"(c[2]), "+f"(c[3])
        : "r"(a[0]), "r"(a[1]), "r"(a[2]), "r"(a[3]), "r"(b[0]), "r"(b[1]));
}

__device__ __forceinline__ unsigned s2u(const void* p) {
    unsigned a;
    asm("{ .reg .u64 t; cvta.to.shared.u64 t, %1; cvt.u32.u64 %0, t; }" : "=r"(a) : "l"(p));
    return a;
}
__device__ __forceinline__ void cpa16(unsigned dst, const void* src) {
    asm volatile("cp.async.cg.shared.global [%0], [%1], 16;" :: "r"(dst), "l"(src));
}
__device__ __forceinline__ void cpcommit() { asm volatile("cp.async.commit_group;"); }
template<int N> __device__ __forceinline__ void cpwait() {
    asm volatile("cp.async.wait_group %0;" :: "n"(N));
}

__device__ __forceinline__ float fsigm(float x)  { return __fdividef(1.0f, 1.0f + __expf(-x)); }
__device__ __forceinline__ float ftanhf(float x) { return 1.0f - __fdividef(2.0f, 1.0f + __expf(2.0f * x)); }

// ---------------------------------------------------------------------------
// One-time converts
// ---------------------------------------------------------------------------
__global__ void conv_w(const float* __restrict__ w, int layer, int dir, int n) {
    int i = blockIdx.x * blockDim.x + threadIdx.x;
    if (i < n) g_wtf[layer][dir][i] = __uint_as_float(f2tf(w[i]));
}
__global__ void conv_x(const float* __restrict__ x) {
    int i = blockIdx.x * blockDim.x + threadIdx.x;   // over [b][t][k]
    if (i < 64 * 512 * 256) {
        int k = i & 255, t = (i >> 8) & 511, b = i >> 17;
        g_xin[((size_t)t * 64 + b) * 256 + k] = __uint_as_float(f2tf(x[i]));
    }
}

__global__ void init_state(const float* __restrict__ h0, int layer) {
    int i = blockIdx.x * blockDim.x + threadIdx.x;
    const int n = 2 * BB * HH;
    if (i < n)
        ((float*)g_h)[i] = __uint_as_float(f2tf(h0[(size_t)layer * n + i]));
    if (i < 128) ((unsigned*)g_flag)[i] = 0;   // reset step flags (also across graph replays)
}

// ---------------------------------------------------------------------------
// Input-projection GEMM, cp.async 2-stage pipeline, tf32 mma.
// Epilogue writes gates in rec layout [dir][slice(32)][t][b(64)][64].
// ---------------------------------------------------------------------------
#define GST (128 * 36)

__global__ __launch_bounds__(256, 2) void gemm_tc(
    int layer, int K, const float* __restrict__ bf_, const float* __restrict__ bb_)
{
    const int dir = blockIdx.z;
    const float* __restrict__ A    = layer ? (const float*)g_x1 : (const float*)g_xin;
    const float* __restrict__ W    = g_wtf[layer][dir];
    const float* __restrict__ bias = dir ? bb_ : bf_;

    extern __shared__ float sm[];
    const unsigned uSm = s2u(sm);

    const int tid  = threadIdx.x;
    const int w    = tid >> 5;
    const int lane = tid & 31;
    const int gp   = lane >> 2;
    const int tg   = lane & 3;
    const int mb   = (w >> 1) * 32;
    const int nb   = (w & 1) * 64;
    const int row0 = blockIdx.y * 128;
    const int col0 = blockIdx.x * 128;

    float c0[8][4], c1[8][4];
#pragma unroll
    for (int ni = 0; ni < 8; ++ni)
#pragma unroll
        for (int q = 0; q < 4; ++q) { c0[ni][q] = 0.0f; c1[ni][q] = 0.0f; }

    auto stage = [&](int k0, int s) {
        const unsigned uA = uSm + (unsigned)(s * (2 * GST)) * 4u;
        const unsigned uB = uA + (unsigned)GST * 4u;
#pragma unroll
        for (int l = 0; l < 4; ++l) {
            int f = tid + l * 256, rr = f >> 3, c4 = f & 7;
            cpa16(uA + (unsigned)(rr * 36 + c4 * 4) * 4u, A + (size_t)(row0 + rr) * K + k0 + c4 * 4);
            cpa16(uB + (unsigned)(rr * 36 + c4 * 4) * 4u, W + (size_t)(col0 + rr) * K + k0 + c4 * 4);
        }
    };
    auto compute = [&](int s) {
        const float* As = sm + s * (2 * GST);
        const float* Bs = As + GST;
#pragma unroll
        for (int kk8 = 0; kk8 < 4; ++kk8) {
            const int kb = kk8 * 8;
            unsigned a0[4], a1[4];
            const int m = mb + gp;
            a0[0] = fu(As[m * 36 + kb + tg]);            a0[1] = fu(As[(m + 8) * 36 + kb + tg]);
            a0[2] = fu(As[m * 36 + kb + tg + 4]);        a0[3] = fu(As[(m + 8) * 36 + kb + tg + 4]);
            a1[0] = fu(As[(m + 16) * 36 + kb + tg]);     a1[1] = fu(As[(m + 24) * 36 + kb + tg]);
            a1[2] = fu(As[(m + 16) * 36 + kb + tg + 4]); a1[3] = fu(As[(m + 24) * 36 + kb + tg + 4]);
#pragma unroll
            for (int ni = 0; ni < 8; ++ni) {
                const int n = nb + ni * 8 + gp;
                unsigned b2[2] = { fu(Bs[n * 36 + kb + tg]), fu(Bs[n * 36 + kb + tg + 4]) };
                mma_tf32(c0[ni], a0, b2);
                mma_tf32(c1[ni], a1, b2);
            }
        }
    };

    const int KT = K >> 5;
    stage(0, 0); cpcommit();
    for (int kt = 0; kt < KT; ++kt) {
        if (kt + 1 < KT) { stage((kt + 1) << 5, (kt + 1) & 1); cpcommit(); cpwait<1>(); }
        else             { cpwait<0>(); }
        __syncthreads();
        compute(kt & 1);
        __syncthreads();
    }

    // Epilogue: bias + store to [dir][slice][t][b][64]
    const int gg = col0 >> 9;   // gate (128-col tile lies within one 512-col gate range)
#pragma unroll
    for (int ni = 0; ni < 8; ++ni) {
        const int col = col0 + nb + ni * 8 + 2 * tg;
        const int ug  = col & 511;          // unit_global
        const int sl  = ug >> 4;
        const int uu  = ug & 15;
        const float bx = bias[col], by = bias[col + 1];
#pragma unroll
        for (int mi = 0; mi < 2; ++mi) {
            float (*cc)[4] = mi ? c1 : c0;
#pragma unroll
            for (int rh = 0; rh < 2; ++rh) {
                const int row = row0 + mb + mi * 16 + rh * 8 + gp;
                float* op = g_gates + ((((size_t)(dir * 32 + sl) * SQ + (row >> 6)) * 64
                                       + (row & 63)) * 64) + gg * 16 + uu;
                *(float2*)op = make_float2(cc[ni][rh * 2] + bx, cc[ni][rh * 2 + 1] + by);
            }
        }
    }
}

// ---------------------------------------------------------------------------
// Persistent recurrent kernel: tf32 mma, flag-line barrier (relaxed poll +
// acq_rel fence), c-state in registers, vectorized h stores.
// 128 blocks: dir = bx>>6, bg = (bx>>5)&1, slice = bx&31.
// ---------------------------------------------------------------------------
#define HSTR 516
#define PSTR 66
#define REC_SMEM ((NBG*HSTR + 64*8*32*2 + NBG*PSTR + NBG*NCOL) * 4)

__global__ __launch_bounds__(256, 1) void lstm_rec_tc(
    const float* __restrict__ whh_f, const float* __restrict__ whh_b,
    const float* __restrict__ c0g, int layer)
{
    extern __shared__ float sm[];
    float* Hs  = sm;                            // [32][516] tf32 h bits        (66KB)
    float* Wpf = sm + NBG * HSTR;               // fragment-packed Whh          (128KB)
    float* Ps  = Wpf + 64 * 8 * 32 * 2;         // [32][66] pre-acts            (8.4KB)
    float* Gs  = Ps + NBG * PSTR;               // [32][64] gates               (8KB)

    const unsigned uHs = s2u(Hs);
    const unsigned uGs = s2u(Gs);

    const int tid  = threadIdx.x;
    const int w    = tid >> 5;
    const int lane = tid & 31;
    const int gp   = lane >> 2;
    const int tg   = lane & 3;
    const int d     = blockIdx.x >> 6;
    const int bg    = (blockIdx.x >> 5) & 1;
    const int slice = blockIdx.x & 31;
    const int grp   = d * 2 + bg;
    const int u0g   = slice * NUNIT;
    const int xall  = (layer == 0);             // layer1 only needs x1 at t==511
    const float* __restrict__ whh = d ? whh_b : whh_f;

    const int m0    = (w >> 2) * 16;            // warp m16 tile (batch rows, 0 or 16)
    const int npair = (w & 3);                  // ntiles {2*npair, 2*npair+1}

    // Pointwise element mapping: thread -> 2 consecutive units (float2)
    const int pidx = tid * 2;
    const int pbl  = pidx >> 4;                 // batch-local 0..31
    const int puu  = pidx & 15;                 // unit-local (even)
    const int pb   = bg * NBG + pbl;
    const int pu   = u0g + puu;

    // c state lives in registers (block-private, never touches DRAM)
    float2 creg = *(const float2*)(c0g + ((size_t)(layer * 2 + d) * 64 + pb) * 512 + pu);

    // Fragment-pack Whh slice once (tf32): Wp[kk(64)][nt(8)][lane]{b0,b1}
    float2* Wp2 = (float2*)Wpf;
    for (int e = tid; e < 64 * 8 * 32; e += 256) {
        int el = e & 31, nt = (e >> 5) & 7, kk = e >> 8;
        int cl = nt * 8 + (el >> 2);
        int k  = kk * 8 + (el & 3);
        size_t jrow = (size_t)((cl >> 4) * 512 + u0g + (cl & 15)) * 512;
        float2 v;
        v.x = __uint_as_float(f2tf(whh[jrow + k]));
        v.y = __uint_as_float(f2tf(whh[jrow + k + 4]));
        Wp2[e] = v;
    }
    __syncthreads();

    for (int step = 0; step < SQ; ++step) {
        const int t   = d ? (SQ - 1 - step) : step;
        const int buf = step & 1;
        const float* hsrc = &g_h[buf][d][bg * NBG][0];

        // 1) Gates prefetch: contiguous 8KB, no h dependency — issue before wait
        {
            const float* gsrc = g_gates + (((size_t)(d * 32 + slice) * SQ + t) * 64
                                           + bg * NBG) * 64;
            cpa16(uGs + (unsigned)tid * 16u,         gsrc + tid * 4);
            cpa16(uGs + (unsigned)(tid + 256) * 16u, gsrc + (tid + 256) * 4);
            cpcommit();                                    // group g0
        }

        // 2) Flag barrier wait: relaxed polls on ONE 128B line + ballot,
        //    then a single acquire fence (orders the g_h reads below).
        if (step > 0) {
            if (tid < 32) {
                unsigned v;
                do {
                    asm volatile("ld.global.relaxed.gpu.u32 %0, [%1];"
                                 : "=r"(v) : "l"(&g_flag[grp][tid]) : "memory");
                } while (__any_sync(0xffffffffu, v < (unsigned)step));
                asm volatile("fence.acq_rel.gpu;" ::: "memory");
            }
            __syncthreads();
        }

        // 3) Stage H[32][512] in 4 k-chunks (cp.async.cg), overlap with mma
        auto stage_chunk = [&](int c) {
#pragma unroll
            for (int l = 0; l < 4; ++l) {
                int f = tid + l * 256, b = f >> 5, q = f & 31;
                cpa16(uHs + (unsigned)(b * HSTR + c * 128 + q * 4) * 4u,
                      hsrc + b * 512 + c * 128 + q * 4);
            }
            cpcommit();
        };
        stage_chunk(0); stage_chunk(1); stage_chunk(2); stage_chunk(3);   // g1..g4

        // 4) tf32 mma over K=512 in 4 chunks
        float c0[4] = {0.f, 0.f, 0.f, 0.f};
        float c1[4] = {0.f, 0.f, 0.f, 0.f};
        const float*  Ha = Hs + (m0 + gp) * HSTR + tg;
        const float2* Wa = Wp2 + (size_t)(npair * 2) * 32 + lane;   // +kk*256; +32 for nt+1
        auto mma_chunk = [&](int cb) {
#pragma unroll
            for (int kk = cb * 16; kk < cb * 16 + 16; ++kk) {
                unsigned a[4];
                a[0] = fu(Ha[kk * 8]);
                a[1] = fu(Ha[kk * 8 + 8 * HSTR]);
                a[2] = fu(Ha[kk * 8 + 4]);
                a[3] = fu(Ha[kk * 8 + 8 * HSTR + 4]);
                float2 b0f = Wa[kk * 256];
                float2 b1f = Wa[kk * 256 + 32];
                unsigned b0[2] = { fu(b0f.x), fu(b0f.y) };
                unsigned b1[2] = { fu(b1f.x), fu(b1f.y) };
                mma_tf32(c0, a, b0);
                mma_tf32(c1, a, b1);
            }
        };
        cpwait<3>(); __syncthreads(); mma_chunk(0);   // g0(gates)+g1 done
        cpwait<2>(); __syncthreads(); mma_chunk(1);
        cpwait<1>(); __syncthreads(); mma_chunk(2);
        cpwait<0>(); __syncthreads(); mma_chunk(3);

        // 5) Pre-activations -> Ps
        {
            const int r  = m0 + gp;
            const int cA = (npair * 2) * 8 + 2 * tg;
            const int cB = cA + 8;
            *(float2*)&Ps[r * PSTR + cA]       = make_float2(c0[0], c0[1]);
            *(float2*)&Ps[(r + 8) * PSTR + cA] = make_float2(c0[2], c0[3]);
            *(float2*)&Ps[r * PSTR + cB]       = make_float2(c1[0], c1[1]);
            *(float2*)&Ps[(r + 8) * PSTR + cB] = make_float2(c1[2], c1[3]);
        }
        __syncthreads();

        // 6) Pointwise gate update: float2 per thread, c in registers
        {
            float2 Pi = *(float2*)&Ps[pbl * PSTR + puu];
            float2 Pf = *(float2*)&Ps[pbl * PSTR + 16 + puu];
            float2 Pg = *(float2*)&Ps[pbl * PSTR + 32 + puu];
            float2 Po = *(float2*)&Ps[pbl * PSTR + 48 + puu];
            float2 Gi = *(float2*)&Gs[pbl * 64 + puu];
            float2 Gf = *(float2*)&Gs[pbl * 64 + 16 + puu];
            float2 Gg = *(float2*)&Gs[pbl * 64 + 32 + puu];
            float2 Go = *(float2*)&Gs[pbl * 64 + 48 + puu];
            float cnx = fsigm(Pf.x + Gf.x) * creg.x
                      + fsigm(Pi.x + Gi.x) * ftanhf(Pg.x + Gg.x);
            float cny = fsigm(Pf.y + Gf.y) * creg.y
                      + fsigm(Pi.y + Gi.y) * ftanhf(Pg.y + Gg.y);
            float hnx = fsigm(Po.x + Go.x) * ftanhf(cnx);
            float hny = fsigm(Po.y + Go.y) * ftanhf(cny);
            creg.x = cnx; creg.y = cny;
            float2 hr2 = make_float2(__uint_as_float(f2tf(hnx)),
                                     __uint_as_float(f2tf(hny)));
            *(float2*)&g_h[buf ^ 1][d][pb][pu] = hr2;
            if (xall | (t == 511))
                *(float2*)(g_x1 + ((size_t)t * BB + pb) * 1024 + d * 512 + pu) = hr2;
        }

        // 7) Publish: release-store after block-wide sync (orders all h writes)
        __syncthreads();
        if (tid == 0) {
            asm volatile("st.global.release.gpu.u32 [%0], %1;"
                         :: "l"(&g_flag[grp][slice]), "r"((unsigned)(step + 1)) : "memory");
        }
    }
}

// ---------------------------------------------------------------------------
// Final FC on last time step
// ---------------------------------------------------------------------------
__global__ void fc_kernel(const float* __restrict__ fc_w, const float* __restrict__ fc_b,
                          float* __restrict__ out)
{
    const int b    = blockIdx.x;
    const int w    = threadIdx.x >> 5;
    const int lane = threadIdx.x & 31;
    const float* __restrict__ x  = g_x1 + ((size_t)(SQ - 1) * BB + b) * 1024;
    const float* __restrict__ wr = fc_w + (size_t)w * 1024;
    float sum = 0.0f;
    for (int k = lane; k < 1024; k += 32) sum = fmaf(x[k], wr[k], sum);
#pragma unroll
    for (int o = 16; o; o >>= 1) sum += __shfl_down_sync(0xffffffffu, sum, o);
    if (lane == 0) out[b * 8 + w] = sum + fc_b[w];
}

// ---------------------------------------------------------------------------
// Launch
// ---------------------------------------------------------------------------
extern "C" void kernel_launch(void* const* d_in, const int* in_sizes, int n_in,
                              void* d_out, int out_size)
{
    const float* input_seq = (const float*)d_in[0];
    const float* h0        = (const float*)d_in[1];
    const float* c0        = (const float*)d_in[2];
    const float* w_ih_0f   = (const float*)d_in[3];
    const float* w_hh_0f   = (const float*)d_in[4];
    const float* b_0f      = (const float*)d_in[5];
    const float* w_ih_0b   = (const float*)d_in[6];
    const float* w_hh_0b   = (const float*)d_in[7];
    const float* b_0b      = (const float*)d_in[8];
    const float* w_ih_1f   = (const float*)d_in[9];
    const float* w_hh_1f   = (const float*)d_in[10];
    const float* b_1f      = (const float*)d_in[11];
    const float* w_ih_1b   = (const float*)d_in[12];
    const float* w_hh_1b   = (const float*)d_in[13];
    const float* b_1b      = (const float*)d_in[14];
    const float* fc_w      = (const float*)d_in[15];
    const float* fc_b      = (const float*)d_in[16];
    (void)in_sizes; (void)n_in; (void)out_size;

    const int GEMM_SMEM = 2 * 2 * GST * 4;
    cudaFuncSetAttribute(gemm_tc,     cudaFuncAttributeMaxDynamicSharedMemorySize, GEMM_SMEM);
    cudaFuncSetAttribute(lstm_rec_tc, cudaFuncAttributeMaxDynamicSharedMemorySize, REC_SMEM);

    conv_w<<<(2048 * 256  + 255) / 256, 256>>>(w_ih_0f, 0, 0, 2048 * 256);
    conv_w<<<(2048 * 256  + 255) / 256, 256>>>(w_ih_0b, 0, 1, 2048 * 256);
    conv_w<<<(2048 * 1024 + 255) / 256, 256>>>(w_ih_1f, 1, 0, 2048 * 1024);
    conv_w<<<(2048 * 1024 + 255) / 256, 256>>>(w_ih_1b, 1, 1, 2048 * 1024);
    conv_x<<<(64 * 512 * 256 + 255) / 256, 256>>>(input_seq);

    dim3 ggrid(16, 256, 2);

    // Layer 0
    init_state<<<64, 1024>>>(h0, 0);
    gemm_tc<<<ggrid, 256, GEMM_SMEM>>>(0, 256, b_0f, b_0b);
    lstm_rec_tc<<<128, 256, REC_SMEM>>>(w_hh_0f, w_hh_0b, c0, 0);

    // Layer 1
    init_state<<<64, 1024>>>(h0, 1);
    gemm_tc<<<ggrid, 256, GEMM_SMEM>>>(1, 1024, b_1f, b_1b);
    lstm_rec_tc<<<128, 256, REC_SMEM>>>(w_hh_1f, w_hh_1b, c0, 1);

    // FC
    fc_kernel<<<64, 256>>>(fc_w, fc_b, (float*)d_out);
}

// round 17
// speedup vs baseline: 1.3224x; 1.3224x over previous
#include <cuda_runtime.h>
#include <math.h>

// Problem dims
#define SQ  512
#define BB  64
#define HH  512
#define G4  2048

// Decomposition: 128 blocks = dir(2) x batch-group(2, 32 batches) x slice(32, 16 units)
#define NBG   32      // batches per group
#define NUNIT 16      // hidden units per slice
#define NCOL  64      // gate columns per block (4 gates x 16 units)

// ---------------------------------------------------------------------------
// Device scratch (allocation-free rule: __device__ globals)
// ---------------------------------------------------------------------------
// gates layout: [dir][slice(32)][t(512)][b(64)][64]  (64 = 4 gates x 16 units)
__device__ float g_gates[2u * SQ * BB * G4];
__device__ float g_x1[(size_t)SQ * BB * 1024];        // layer output, tf32-rounded bits
__device__ float g_h[2][2][BB][HH];                   // double-buffered h (tf32-rounded)
__device__ float g_wtf[2][2][2048 * 1024];            // W_ih tf32 bits [layer][dir][j*K+k]
__device__ float g_xin[(size_t)SQ * BB * 256];        // input_seq transposed+tf32
__device__ unsigned g_bcnt[4];                        // per-(dir,bg) barrier counters
__device__ unsigned g_bgen[4];                        // per-(dir,bg) barrier generations

// ---------------------------------------------------------------------------
// Helpers
// ---------------------------------------------------------------------------
__device__ __forceinline__ unsigned f2tf(float x) {
    unsigned u; asm("cvt.rna.tf32.f32 %0, %1;" : "=r"(u) : "f"(x)); return u;
}
__device__ __forceinline__ unsigned fu(float x) { return __float_as_uint(x); }

__device__ __forceinline__ void mma_tf32(float* c, const unsigned* a, const unsigned* b) {
    asm("mma.sync.aligned.m16n8k8.row.col.f32.tf32.tf32.f32 "
        "{%0,%1,%2,%3}, {%4,%5,%6,%7}, {%8,%9}, {%0,%1,%2,%3};"
        : "+f"(c[0]), "+f"(c[1]), "+f"(c[2]), "+f"(c[3])
        : "r"(a[0]), "r"(a[1]), "r"(a[2]), "r"(a[3]), "r"(b[0]), "r"(b[1]));
}

__device__ __forceinline__ unsigned s2u(const void* p) {
    unsigned a;
    asm("{ .reg .u64 t; cvta.to.shared.u64 t, %1; cvt.u32.u64 %0, t; }" : "=r"(a) : "l"(p));
    return a;
}
__device__ __forceinline__ void cpa16(unsigned dst, const void* src) {
    asm volatile("cp.async.cg.shared.global [%0], [%1], 16;" :: "r"(dst), "l"(src));
}
__device__ __forceinline__ void cpcommit() { asm volatile("cp.async.commit_group;"); }
template<int N> __device__ __forceinline__ void cpwait() {
    asm volatile("cp.async.wait_group %0;" :: "n"(N));
}

__device__ __forceinline__ float fsigm(float x)  { return __fdividef(1.0f, 1.0f + __expf(-x)); }
__device__ __forceinline__ float ftanhf(float x) { return 1.0f - __fdividef(2.0f, 1.0f + __expf(2.0f * x)); }

// R15-proven sense-reversing barrier, per group of 32 blocks
__device__ __forceinline__ void group_barrier(int grp) {
    __syncthreads();
    if (threadIdx.x == 0) {
        __threadfence();
        unsigned gen = ((volatile unsigned*)g_bgen)[grp];
        unsigned prev = atomicAdd(&g_bcnt[grp], 1u);
        if (prev == 31u) {
            ((volatile unsigned*)g_bcnt)[grp] = 0u;
            __threadfence();
            atomicAdd(&g_bgen[grp], 1u);
        } else {
            while (((volatile unsigned*)g_bgen)[grp] == gen) {}
        }
        __threadfence();
    }
    __syncthreads();
}

// ---------------------------------------------------------------------------
// One-time converts (merged to control launch ordering for ncu: rec0 = launch 4)
// ---------------------------------------------------------------------------
// Launch 1: all four W_ih conversions in one grid
__global__ void conv_all(const float* __restrict__ w0f, const float* __restrict__ w0b,
                         const float* __restrict__ w1f, const float* __restrict__ w1b)
{
    int i = blockIdx.x * blockDim.x + threadIdx.x;
    if (i < 524288)        g_wtf[0][0][i]           = __uint_as_float(f2tf(w0f[i]));
    else if (i < 1048576)  g_wtf[0][1][i - 524288]  = __uint_as_float(f2tf(w0b[i - 524288]));
    else if (i < 3145728)  g_wtf[1][0][i - 1048576] = __uint_as_float(f2tf(w1f[i - 1048576]));
    else if (i < 5242880)  g_wtf[1][1][i - 3145728] = __uint_as_float(f2tf(w1b[i - 3145728]));
}

// Launch 2: input transpose+convert, layer-0 h init, barrier reset
__global__ void conv_x_init(const float* __restrict__ x, const float* __restrict__ h0)
{
    int i = blockIdx.x * blockDim.x + threadIdx.x;
    if (i < 64 * 512 * 256) {                         // [b][t][k] -> [(t*64+b)*256+k]
        int k = i & 255, t = (i >> 8) & 511, b = i >> 17;
        g_xin[((size_t)t * 64 + b) * 256 + k] = __uint_as_float(f2tf(x[i]));
    }
    if (i < 2 * BB * HH)
        ((float*)g_h)[i] = __uint_as_float(f2tf(h0[i]));   // layer 0 dirs
    if (i < 4) { g_bcnt[i] = 0; g_bgen[i] = 0; }
}

// Layer-1 h init + barrier reset (launch 5)
__global__ void init_state(const float* __restrict__ h0, int layer) {
    int i = blockIdx.x * blockDim.x + threadIdx.x;
    const int n = 2 * BB * HH;
    if (i < n)
        ((float*)g_h)[i] = __uint_as_float(f2tf(h0[(size_t)layer * n + i]));
    if (i < 4) { g_bcnt[i] = 0; g_bgen[i] = 0; }
}

// ---------------------------------------------------------------------------
// Input-projection GEMM, cp.async 2-stage pipeline, tf32 mma.
// Epilogue writes gates in rec layout [dir][slice(32)][t][b(64)][64].
// ---------------------------------------------------------------------------
#define GST (128 * 36)

__global__ __launch_bounds__(256, 2) void gemm_tc(
    int layer, int K, const float* __restrict__ bf_, const float* __restrict__ bb_)
{
    const int dir = blockIdx.z;
    const float* __restrict__ A    = layer ? (const float*)g_x1 : (const float*)g_xin;
    const float* __restrict__ W    = g_wtf[layer][dir];
    const float* __restrict__ bias = dir ? bb_ : bf_;

    extern __shared__ float sm[];
    const unsigned uSm = s2u(sm);

    const int tid  = threadIdx.x;
    const int w    = tid >> 5;
    const int lane = tid & 31;
    const int gp   = lane >> 2;
    const int tg   = lane & 3;
    const int mb   = (w >> 1) * 32;
    const int nb   = (w & 1) * 64;
    const int row0 = blockIdx.y * 128;
    const int col0 = blockIdx.x * 128;

    float c0[8][4], c1[8][4];
#pragma unroll
    for (int ni = 0; ni < 8; ++ni)
#pragma unroll
        for (int q = 0; q < 4; ++q) { c0[ni][q] = 0.0f; c1[ni][q] = 0.0f; }

    auto stage = [&](int k0, int s) {
        const unsigned uA = uSm + (unsigned)(s * (2 * GST)) * 4u;
        const unsigned uB = uA + (unsigned)GST * 4u;
#pragma unroll
        for (int l = 0; l < 4; ++l) {
            int f = tid + l * 256, rr = f >> 3, c4 = f & 7;
            cpa16(uA + (unsigned)(rr * 36 + c4 * 4) * 4u, A + (size_t)(row0 + rr) * K + k0 + c4 * 4);
            cpa16(uB + (unsigned)(rr * 36 + c4 * 4) * 4u, W + (size_t)(col0 + rr) * K + k0 + c4 * 4);
        }
    };
    auto compute = [&](int s) {
        const float* As = sm + s * (2 * GST);
        const float* Bs = As + GST;
#pragma unroll
        for (int kk8 = 0; kk8 < 4; ++kk8) {
            const int kb = kk8 * 8;
            unsigned a0[4], a1[4];
            const int m = mb + gp;
            a0[0] = fu(As[m * 36 + kb + tg]);            a0[1] = fu(As[(m + 8) * 36 + kb + tg]);
            a0[2] = fu(As[m * 36 + kb + tg + 4]);        a0[3] = fu(As[(m + 8) * 36 + kb + tg + 4]);
            a1[0] = fu(As[(m + 16) * 36 + kb + tg]);     a1[1] = fu(As[(m + 24) * 36 + kb + tg]);
            a1[2] = fu(As[(m + 16) * 36 + kb + tg + 4]); a1[3] = fu(As[(m + 24) * 36 + kb + tg + 4]);
#pragma unroll
            for (int ni = 0; ni < 8; ++ni) {
                const int n = nb + ni * 8 + gp;
                unsigned b2[2] = { fu(Bs[n * 36 + kb + tg]), fu(Bs[n * 36 + kb + tg + 4]) };
                mma_tf32(c0[ni], a0, b2);
                mma_tf32(c1[ni], a1, b2);
            }
        }
    };

    const int KT = K >> 5;
    stage(0, 0); cpcommit();
    for (int kt = 0; kt < KT; ++kt) {
        if (kt + 1 < KT) { stage((kt + 1) << 5, (kt + 1) & 1); cpcommit(); cpwait<1>(); }
        else             { cpwait<0>(); }
        __syncthreads();
        compute(kt & 1);
        __syncthreads();
    }

    // Epilogue: bias + store to [dir][slice][t][b][64]
    const int gg = col0 >> 9;   // gate (128-col tile lies within one 512-col gate range)
#pragma unroll
    for (int ni = 0; ni < 8; ++ni) {
        const int col = col0 + nb + ni * 8 + 2 * tg;
        const int ug  = col & 511;          // unit_global
        const int sl  = ug >> 4;
        const int uu  = ug & 15;
        const float bx = bias[col], by = bias[col + 1];
#pragma unroll
        for (int mi = 0; mi < 2; ++mi) {
            float (*cc)[4] = mi ? c1 : c0;
#pragma unroll
            for (int rh = 0; rh < 2; ++rh) {
                const int row = row0 + mb + mi * 16 + rh * 8 + gp;
                float* op = g_gates + ((((size_t)(dir * 32 + sl) * SQ + (row >> 6)) * 64
                                       + (row & 63)) * 64) + gg * 16 + uu;
                *(float2*)op = make_float2(cc[ni][rh * 2] + bx, cc[ni][rh * 2 + 1] + by);
            }
        }
    }
}

// ---------------------------------------------------------------------------
// Persistent recurrent kernel: tf32 mma, R15 atomic group barrier,
// c-state in registers, float2 h stores, layer-1 x1 skip.
// 128 blocks: dir = bx>>6, bg = (bx>>5)&1, slice = bx&31.
// ---------------------------------------------------------------------------
#define HSTR 516
#define PSTR 66
#define REC_SMEM ((NBG*HSTR + 64*8*32*2 + NBG*PSTR + NBG*NCOL) * 4)

__global__ __launch_bounds__(256, 1) void lstm_rec_tc(
    const float* __restrict__ whh_f, const float* __restrict__ whh_b,
    const float* __restrict__ c0g, int layer)
{
    extern __shared__ float sm[];
    float* Hs  = sm;                            // [32][516] tf32 h bits        (66KB)
    float* Wpf = sm + NBG * HSTR;               // fragment-packed Whh          (128KB)
    float* Ps  = Wpf + 64 * 8 * 32 * 2;         // [32][66] pre-acts            (8.4KB)
    float* Gs  = Ps + NBG * PSTR;               // [32][64] gates               (8KB)

    const unsigned uHs = s2u(Hs);
    const unsigned uGs = s2u(Gs);

    const int tid  = threadIdx.x;
    const int w    = tid >> 5;
    const int lane = tid & 31;
    const int gp   = lane >> 2;
    const int tg   = lane & 3;
    const int d     = blockIdx.x >> 6;
    const int bg    = (blockIdx.x >> 5) & 1;
    const int slice = blockIdx.x & 31;
    const int grp   = d * 2 + bg;
    const int u0g   = slice * NUNIT;
    const int xall  = (layer == 0);             // layer1 only needs x1 at t==511
    const float* __restrict__ whh = d ? whh_b : whh_f;

    const int m0    = (w >> 2) * 16;            // warp m16 tile (batch rows, 0 or 16)
    const int npair = (w & 3);                  // ntiles {2*npair, 2*npair+1}

    // Pointwise element mapping: thread -> 2 consecutive units (float2)
    const int pidx = tid * 2;
    const int pbl  = pidx >> 4;                 // batch-local 0..31
    const int puu  = pidx & 15;                 // unit-local (even)
    const int pb   = bg * NBG + pbl;
    const int pu   = u0g + puu;

    // c state lives in registers (block-private, never touches DRAM)
    float2 creg = *(const float2*)(c0g + ((size_t)(layer * 2 + d) * 64 + pb) * 512 + pu);

    // Fragment-pack Whh slice once (tf32): Wp[kk(64)][nt(8)][lane]{b0,b1}
    float2* Wp2 = (float2*)Wpf;
    for (int e = tid; e < 64 * 8 * 32; e += 256) {
        int el = e & 31, nt = (e >> 5) & 7, kk = e >> 8;
        int cl = nt * 8 + (el >> 2);
        int k  = kk * 8 + (el & 3);
        size_t jrow = (size_t)((cl >> 4) * 512 + u0g + (cl & 15)) * 512;
        float2 v;
        v.x = __uint_as_float(f2tf(whh[jrow + k]));
        v.y = __uint_as_float(f2tf(whh[jrow + k + 4]));
        Wp2[e] = v;
    }
    __syncthreads();

    for (int step = 0; step < SQ; ++step) {
        const int t   = d ? (SQ - 1 - step) : step;
        const int buf = step & 1;
        const float* hsrc = &g_h[buf][d][bg * NBG][0];

        // 1) Gates prefetch: contiguous 8KB, no h dependency
        {
            const float* gsrc = g_gates + (((size_t)(d * 32 + slice) * SQ + t) * 64
                                           + bg * NBG) * 64;
            cpa16(uGs + (unsigned)tid * 16u,         gsrc + tid * 4);
            cpa16(uGs + (unsigned)(tid + 256) * 16u, gsrc + (tid + 256) * 4);
            cpcommit();                                    // group g0
        }

        // 2) Stage H[32][512] in 4 k-chunks (cp.async.cg), overlap with mma
        auto stage_chunk = [&](int c) {
#pragma unroll
            for (int l = 0; l < 4; ++l) {
                int f = tid + l * 256, b = f >> 5, q = f & 31;
                cpa16(uHs + (unsigned)(b * HSTR + c * 128 + q * 4) * 4u,
                      hsrc + b * 512 + c * 128 + q * 4);
            }
            cpcommit();
        };
        stage_chunk(0); stage_chunk(1); stage_chunk(2); stage_chunk(3);   // g1..g4

        // 3) tf32 mma over K=512 in 4 chunks
        float c0[4] = {0.f, 0.f, 0.f, 0.f};
        float c1[4] = {0.f, 0.f, 0.f, 0.f};
        const float*  Ha = Hs + (m0 + gp) * HSTR + tg;
        const float2* Wa = Wp2 + (size_t)(npair * 2) * 32 + lane;   // +kk*256; +32 for nt+1
        auto mma_chunk = [&](int cb) {
#pragma unroll
            for (int kk = cb * 16; kk < cb * 16 + 16; ++kk) {
                unsigned a[4];
                a[0] = fu(Ha[kk * 8]);
                a[1] = fu(Ha[kk * 8 + 8 * HSTR]);
                a[2] = fu(Ha[kk * 8 + 4]);
                a[3] = fu(Ha[kk * 8 + 8 * HSTR + 4]);
                float2 b0f = Wa[kk * 256];
                float2 b1f = Wa[kk * 256 + 32];
                unsigned b0[2] = { fu(b0f.x), fu(b0f.y) };
                unsigned b1[2] = { fu(b1f.x), fu(b1f.y) };
                mma_tf32(c0, a, b0);
                mma_tf32(c1, a, b1);
            }
        };
        cpwait<3>(); __syncthreads(); mma_chunk(0);   // g0(gates)+g1 done
        cpwait<2>(); __syncthreads(); mma_chunk(1);
        cpwait<1>(); __syncthreads(); mma_chunk(2);
        cpwait<0>(); __syncthreads(); mma_chunk(3);

        // 4) Pre-activations -> Ps
        {
            const int r  = m0 + gp;
            const int cA = (npair * 2) * 8 + 2 * tg;
            const int cB = cA + 8;
            *(float2*)&Ps[r * PSTR + cA]       = make_float2(c0[0], c0[1]);
            *(float2*)&Ps[(r + 8) * PSTR + cA] = make_float2(c0[2], c0[3]);
            *(float2*)&Ps[r * PSTR + cB]       = make_float2(c1[0], c1[1]);
            *(float2*)&Ps[(r + 8) * PSTR + cB] = make_float2(c1[2], c1[3]);
        }
        __syncthreads();

        // 5) Pointwise gate update: float2 per thread, c in registers
        {
            float2 Pi = *(float2*)&Ps[pbl * PSTR + puu];
            float2 Pf = *(float2*)&Ps[pbl * PSTR + 16 + puu];
            float2 Pg = *(float2*)&Ps[pbl * PSTR + 32 + puu];
            float2 Po = *(float2*)&Ps[pbl * PSTR + 48 + puu];
            float2 Gi = *(float2*)&Gs[pbl * 64 + puu];
            float2 Gf = *(float2*)&Gs[pbl * 64 + 16 + puu];
            float2 Gg = *(float2*)&Gs[pbl * 64 + 32 + puu];
            float2 Go = *(float2*)&Gs[pbl * 64 + 48 + puu];
            float cnx = fsigm(Pf.x + Gf.x) * creg.x
                      + fsigm(Pi.x + Gi.x) * ftanhf(Pg.x + Gg.x);
            float cny = fsigm(Pf.y + Gf.y) * creg.y
                      + fsigm(Pi.y + Gi.y) * ftanhf(Pg.y + Gg.y);
            float hnx = fsigm(Po.x + Go.x) * ftanhf(cnx);
            float hny = fsigm(Po.y + Go.y) * ftanhf(cny);
            creg.x = cnx; creg.y = cny;
            float2 hr2 = make_float2(__uint_as_float(f2tf(hnx)),
                                     __uint_as_float(f2tf(hny)));
            *(float2*)&g_h[buf ^ 1][d][pb][pu] = hr2;
            if (xall | (t == 511))
                *(float2*)(g_x1 + ((size_t)t * BB + pb) * 1024 + d * 512 + pu) = hr2;
        }

        // 6) Group barrier (R15-proven atomic sense-reversing, 32 blocks/group)
        group_barrier(grp);
    }
}

// ---------------------------------------------------------------------------
// Final FC on last time step
// ---------------------------------------------------------------------------
__global__ void fc_kernel(const float* __restrict__ fc_w, const float* __restrict__ fc_b,
                          float* __restrict__ out)
{
    const int b    = blockIdx.x;
    const int w    = threadIdx.x >> 5;
    const int lane = threadIdx.x & 31;
    const float* __restrict__ x  = g_x1 + ((size_t)(SQ - 1) * BB + b) * 1024;
    const float* __restrict__ wr = fc_w + (size_t)w * 1024;
    float sum = 0.0f;
    for (int k = lane; k < 1024; k += 32) sum = fmaf(x[k], wr[k], sum);
#pragma unroll
    for (int o = 16; o; o >>= 1) sum += __shfl_down_sync(0xffffffffu, sum, o);
    if (lane == 0) out[b * 8 + w] = sum + fc_b[w];
}

// ---------------------------------------------------------------------------
// Launch — ordered so lstm_rec_tc(layer 0) is launch #4 (ncu captures launch 4)
// ---------------------------------------------------------------------------
extern "C" void kernel_launch(void* const* d_in, const int* in_sizes, int n_in,
                              void* d_out, int out_size)
{
    const float* input_seq = (const float*)d_in[0];
    const float* h0        = (const float*)d_in[1];
    const float* c0        = (const float*)d_in[2];
    const float* w_ih_0f   = (const float*)d_in[3];
    const float* w_hh_0f   = (const float*)d_in[4];
    const float* b_0f      = (const float*)d_in[5];
    const float* w_ih_0b   = (const float*)d_in[6];
    const float* w_hh_0b   = (const float*)d_in[7];
    const float* b_0b      = (const float*)d_in[8];
    const float* w_ih_1f   = (const float*)d_in[9];
    const float* w_hh_1f   = (const float*)d_in[10];
    const float* b_1f      = (const float*)d_in[11];
    const float* w_ih_1b   = (const float*)d_in[12];
    const float* w_hh_1b   = (const float*)d_in[13];
    const float* b_1b      = (const float*)d_in[14];
    const float* fc_w      = (const float*)d_in[15];
    const float* fc_b      = (const float*)d_in[16];
    (void)in_sizes; (void)n_in; (void)out_size;

    const int GEMM_SMEM = 2 * 2 * GST * 4;
    cudaFuncSetAttribute(gemm_tc,     cudaFuncAttributeMaxDynamicSharedMemorySize, GEMM_SMEM);
    cudaFuncSetAttribute(lstm_rec_tc, cudaFuncAttributeMaxDynamicSharedMemorySize, REC_SMEM);

    dim3 ggrid(16, 256, 2);

    // 1: all weight converts     2: x convert + layer-0 init
    conv_all<<<20480, 256>>>(w_ih_0f, w_ih_0b, w_ih_1f, w_ih_1b);
    conv_x_init<<<32768, 256>>>(input_seq, h0);

    // 3: gemm0   4: rec0  <-- profiled launch
    gemm_tc<<<ggrid, 256, GEMM_SMEM>>>(0, 256, b_0f, b_0b);
    lstm_rec_tc<<<128, 256, REC_SMEM>>>(w_hh_0f, w_hh_0b, c0, 0);

    // 5: init1   6: gemm1   7: rec1
    init_state<<<64, 1024>>>(h0, 1);
    gemm_tc<<<ggrid, 256, GEMM_SMEM>>>(1, 1024, b_1f, b_1b);
    lstm_rec_tc<<<128, 256, REC_SMEM>>>(w_hh_1f, w_hh_1b, c0, 1);

    // 8: fc
    fc_kernel<<<64, 256>>>(fc_w, fc_b, (float*)d_out);
}